// round 5
// baseline (speedup 1.0000x reference)
#include <cuda_runtime.h>
#include <math.h>

#define NUM_FEATURES 10
#define XSTRIDE 12               // padded row stride (floats) -> 48B, 16B aligned
#define EMBED 256
#define MAXLEN 366
#define PE_ROWS (MAXLEN + 1)
#define OUT_DIM (2 * EMBED)
#define GRID 740                 // 148 SMs x 5 resident blocks, single wave
#define MAX_TOK_PER_BLOCK 180    // ceil(131072/740)=178, rounded up

// Positional-encoding table: row 0 zeros, rows 1..366 sin/cos for pos 0..365.
__device__ float g_pe[PE_ROWS * EMBED];

// ---------------------------------------------------------------------------
// Fill PE table (single precision MUFU path, ~5e-5 abs err vs fp32 numpy).
// ---------------------------------------------------------------------------
__global__ void fill_pe_kernel() {
    int idx = blockIdx.x * blockDim.x + threadIdx.x;
    const int pairs = EMBED / 2;
    if (idx >= PE_ROWS * pairs) return;
    int row = idx / pairs;
    int i   = idx - row * pairs;
    float s = 0.0f, c = 0.0f;
    if (row > 0) {
        const float k = -(logf(10000.0f) / (float)EMBED);
        float div = expf((float)(2 * i) * k);
        sincosf((float)(row - 1) * div, &s, &c);
    }
    g_pe[row * EMBED + 2 * i]     = s;
    g_pe[row * EMBED + 2 * i + 1] = c;
}

// ---------------------------------------------------------------------------
// Packed f32x2 helpers (sm_103a dual FMA; PTX-only, ptxas won't auto-fuse).
// ---------------------------------------------------------------------------
__device__ __forceinline__ unsigned long long pack2(float a, float b) {
    unsigned long long r;
    asm("mov.b64 %0, {%1, %2};" : "=l"(r) : "f"(a), "f"(b));
    return r;
}
__device__ __forceinline__ unsigned long long fma2(unsigned long long a,
                                                   unsigned long long b,
                                                   unsigned long long c) {
    unsigned long long d;
    asm("fma.rn.f32x2 %0, %1, %2, %3;" : "=l"(d) : "l"(a), "l"(b), "l"(c));
    return d;
}
__device__ __forceinline__ float2 unpack2(unsigned long long v) {
    float lo, hi;
    asm("mov.b64 {%0, %1}, %2;" : "=f"(lo), "=f"(hi) : "l"(v));
    return make_float2(lo, hi);
}

// ---------------------------------------------------------------------------
// Main kernel.
// Feature-paired packed math: accumulator lane0 sums even features, lane1 odd
// features (bias folded into lane0 init); one lane-add finishes each channel.
// x is staged UN-duplicated (stride-12 rows) and read with only 3 broadcast
// LDS per token (2x LDS.128 + 1x LDS.64) -- the main L1-wavefront cut vs R4.
// PE gather for token t+2 is prefetched before token t's FMA chain.
// ---------------------------------------------------------------------------
__global__ __launch_bounds__(256, 5)
void bert_embed_kernel(const float* __restrict__ x,     // [ntok, 10]
                       const int*   __restrict__ doy,   // [ntok]
                       const float* __restrict__ W,     // [256, 10]
                       const float* __restrict__ bias_g,// [256]
                       float*       __restrict__ out,   // [ntok, 512]
                       int ntok) {
    __shared__ __align__(16) float sx[MAX_TOK_PER_BLOCK * XSTRIDE];
    __shared__ int sdoy[MAX_TOK_PER_BLOCK];

    const int per = (ntok + GRID - 1) / GRID;      // 178
    const int t0  = blockIdx.x * per;
    const int cnt = min(per, ntok - t0);
    if (cnt <= 0) return;

    // Stage x into stride-12 rows + doy. Coalesced LDG reads.
    for (int i = threadIdx.x; i < cnt * NUM_FEATURES; i += blockDim.x) {
        int row = i / NUM_FEATURES;
        int col = i - row * NUM_FEATURES;
        sx[row * XSTRIDE + col] = __ldg(x + (size_t)t0 * NUM_FEATURES + i);
    }
    for (int i = threadIdx.x; i < cnt; i += blockDim.x)
        sdoy[i] = __ldg(doy + t0 + i);

    const int e_lane = threadIdx.x & 127;
    const int t_lane = threadIdx.x >> 7;           // 0 or 1
    const int e0 = e_lane * 2;

    // Feature-pair-packed weights for this thread's 2 channels (10 b64 regs).
    unsigned long long wp0[5], wp1[5];
#pragma unroll
    for (int p = 0; p < 5; p++) {
        wp0[p] = pack2(__ldg(W + (e0 + 0) * NUM_FEATURES + 2 * p),
                       __ldg(W + (e0 + 0) * NUM_FEATURES + 2 * p + 1));
        wp1[p] = pack2(__ldg(W + (e0 + 1) * NUM_FEATURES + 2 * p),
                       __ldg(W + (e0 + 1) * NUM_FEATURES + 2 * p + 1));
    }
    const float bias0 = __ldg(bias_g + e0);
    const float bias1 = __ldg(bias_g + e0 + 1);

    __syncthreads();

    int tt = t_lane;
    // Prologue: gather PE for the first token.
    float2 pev = make_float2(0.f, 0.f);
    if (tt < cnt)
        pev = *reinterpret_cast<const float2*>(&g_pe[sdoy[tt] * EMBED + e0]);

    for (; tt < cnt; tt += 2) {
        // Prefetch next iteration's PE gather (row 0 = zeros is a safe dummy).
        const int tn = tt + 2;
        const int dn = (tn < cnt) ? sdoy[tn] : 0;
        const float2 pev_next =
            *reinterpret_cast<const float2*>(&g_pe[dn * EMBED + e0]);

        // x features: 3 broadcast shared loads (f0..f3, f4..f7, f8..f9).
        const float* xr = sx + tt * XSTRIDE;
        float4 q0 = *reinterpret_cast<const float4*>(xr);
        float4 q1 = *reinterpret_cast<const float4*>(xr + 4);
        float2 q2 = *reinterpret_cast<const float2*>(xr + 8);
        unsigned long long xp[5];
        xp[0] = pack2(q0.x, q0.y);   // adjacent float4 halves: pack is ~free
        xp[1] = pack2(q0.z, q0.w);
        xp[2] = pack2(q1.x, q1.y);
        xp[3] = pack2(q1.z, q1.w);
        xp[4] = pack2(q2.x, q2.y);

        // lane0 accumulates even features (+bias), lane1 odd features.
        unsigned long long a0 = pack2(bias0, 0.0f);
        unsigned long long a1 = pack2(bias1, 0.0f);
#pragma unroll
        for (int p = 0; p < 5; p++) {
            a0 = fma2(xp[p], wp0[p], a0);
            a1 = fma2(xp[p], wp1[p], a1);
        }
        float2 r0 = unpack2(a0);
        float2 r1 = unpack2(a1);

        float* op = out + (size_t)(t0 + tt) * OUT_DIM;
        __stcs(reinterpret_cast<float2*>(op + e0),
               make_float2(r0.x + r0.y, r1.x + r1.y));
        __stcs(reinterpret_cast<float2*>(op + EMBED + e0), pev);

        pev = pev_next;
    }
}

extern "C" void kernel_launch(void* const* d_in, const int* in_sizes, int n_in,
                              void* d_out, int out_size) {
    const float* x    = (const float*)d_in[0];   // input_sequence [256,512,10]
    const int*   doy  = (const int*)  d_in[1];   // doy_sequence   [256,512]
    const float* W    = (const float*)d_in[2];   // [256,10]
    const float* b    = (const float*)d_in[3];   // [256]
    float*       out  = (float*)d_out;           // [256,512,512]

    const int ntok = in_sizes[1];                // 131072 tokens

    const int pe_threads = PE_ROWS * (EMBED / 2);
    fill_pe_kernel<<<(pe_threads + 255) / 256, 256>>>();

    bert_embed_kernel<<<GRID, 256>>>(x, doy, W, b, out, ntok);
}